// round 11
// baseline (speedup 1.0000x reference)
#include <cuda_runtime.h>
#include <math.h>

#define WDIM 512
#define LDIM 512
#define WL   (WDIM * LDIM)      // 262144 pixels
#define NTGT 64
#define TPB  256
#define NBLK 512                // 32 i-tiles x 16 j-tiles (tile 16r x 32c)
#define NWARPTOT (NBLK * 8)

__device__ float        g_accum;  // zero-init; publisher resets
__device__ unsigned int g_done;   // zero-init; publisher resets

// logit(0.1) = ln(0.1/0.9)
#define LOGIT_THRESH (-2.1972245773362196f)

// ---------------------------------------------------------------------------
// Warp-autonomous kernel: 2 pixels x 2 anchors per thread; each warp owns a
// 2-row x 32-px strip, culls the 64 targets against its own bbox (shfl +
// ballot compaction, no block barriers), accumulates via per-warp atomics.
// ---------------------------------------------------------------------------
__global__ __launch_bounds__(TPB, 4) void loss_kernel(
    const float* __restrict__ psm,    // [2, W, L]
    const float* __restrict__ rm,     // [14, W, L]
    const float* __restrict__ anc,    // [W, L, 2, 7]
    const float* __restrict__ Tm,     // [4, 4]
    const float* __restrict__ target, // [64, 7]
    float* __restrict__ out)
{
    const int tid  = threadIdx.x;
    const int lane = tid & 31;
    const int w    = tid >> 5;            // warp 0..7

    // ---- mapping: warp w covers rows {2w, 2w+1} of the 16x32 tile ----
    const int tile_i = blockIdx.x >> 4;            // 0..31
    const int tile_j = blockIdx.x & 15;            // 0..15
    const int i  = tile_i * 16 + w * 2 + (lane >> 4);
    const int jp = tile_j * 16 + (lane & 15);      // j-pair index
    const int pix0 = i * LDIM + jp * 2;

    // ---- front-batch streaming loads ----
    float2 rc[14];
#pragma unroll
    for (int c = 0; c < 14; c++)
        rc[c] = *(const float2*)(rm + (size_t)c * WL + pix0);

    const float2 sA = *(const float2*)(psm + pix0);
    const float2 sB = *(const float2*)(psm + WL + pix0);

    // ---- anchor grid parameters (uniform, cached) ----
    const float x0   = anc[0];
    const float y0   = anc[1];
    const float cz   = anc[2];
    const float ah   = anc[3];
    const float aw   = anc[4];
    const float al   = anc[5];
    const float yaw0 = anc[6];
    const float yaw1 = anc[13];
    const float dxs  = anc[512 * 14] - x0;
    const float dys  = anc[14 + 1]   - y0;

    const float dg = sqrtf(aw * aw + al * al);
    const float ax = fmaf((float)i, dxs, x0);
    const float ay_p[2] = { fmaf((float)(jp * 2),     dys, y0),
                            fmaf((float)(jp * 2 + 1), dys, y0) };

    // ---- stage target standup boxes to smem (threads 0..63), SoA ----
    __shared__ float s_tx1[NTGT], s_ty1[NTGT], s_tx2[NTGT], s_ty2[NTGT],
                     s_tar[NTGT];
    if (tid < NTGT) {
        const float* t = target + tid * 7;
        float X = t[0], Y = t[1];
        float ww = t[4], ll = t[5];
        float c, s;
        __sincosf(t[6], &s, &c);
        float ex = 0.5f * (fabsf(c) * ll + fabsf(s) * ww);
        float ey = 0.5f * (fabsf(s) * ll + fabsf(c) * ww);
        s_tx1[tid] = X - ex;  s_tx2[tid] = X + ex;
        s_ty1[tid] = Y - ey;  s_ty2[tid] = Y + ey;
        s_tar[tid] = (2.0f * ex) * (2.0f * ey);
    }
    __syncthreads();   // the ONLY block barrier (overlaps rm loads in flight)

    const float T00 = Tm[0], T01 = Tm[1], T02 = Tm[2], T03 = Tm[3];
    const float T10 = Tm[4], T11 = Tm[5], T12 = Tm[6], T13 = Tm[7];

    // ---- decode 4 boxes: b = p*2 + a ----
    float px1[4], py1[4], px2[4], py2[4], areat[4], wlog[4];

#pragma unroll
    for (int p = 0; p < 2; p++) {
#pragma unroll
        for (int a = 0; a < 2; a++) {
            const int b = p * 2 + a;

            float xl = (a == 0) ? (p == 0 ? sA.x : sA.y)
                                : (p == 0 ? sB.x : sB.y);
            wlog[b] = (xl > LOGIT_THRESH)
                        ? -__logf(1.0f + __expf(xl)) : 0.0f;

            float d0 = (p == 0) ? rc[a * 7 + 0].x : rc[a * 7 + 0].y;
            float d1 = (p == 0) ? rc[a * 7 + 1].x : rc[a * 7 + 1].y;
            float d2 = (p == 0) ? rc[a * 7 + 2].x : rc[a * 7 + 2].y;
            float d3 = (p == 0) ? rc[a * 7 + 3].x : rc[a * 7 + 3].y;
            float d4 = (p == 0) ? rc[a * 7 + 4].x : rc[a * 7 + 4].y;
            float d5 = (p == 0) ? rc[a * 7 + 5].x : rc[a * 7 + 5].y;
            float d6 = (p == 0) ? rc[a * 7 + 6].x : rc[a * 7 + 6].y;

            float X = fmaf(d0, dg, ax);
            float Y = fmaf(d1, dg, ay_p[p]);
            float Z = fmaf(d2, ah, cz);
            float hh = __expf(d3) * ah;
            float ww = __expf(d4) * aw;
            float ll = __expf(d5) * al;

            float c, s;
            __sincosf(d6 + ((a == 0) ? yaw0 : yaw1), &s, &c);

            float bx = fmaf(T00, X, fmaf(T01, Y, fmaf(T02, Z, T03)));
            float by = fmaf(T10, X, fmaf(T11, Y, fmaf(T12, Z, T13)));
            float ex = 0.5f * (fabsf(fmaf(T00, c,  T01 * s)) * ll +
                               fabsf(fmaf(T01, c, -T00 * s)) * ww +
                               fabsf(T02) * hh);
            float ey = 0.5f * (fabsf(fmaf(T10, c,  T11 * s)) * ll +
                               fabsf(fmaf(T11, c, -T10 * s)) * ww +
                               fabsf(T12) * hh);

            px1[b] = bx - ex;  px2[b] = bx + ex;
            py1[b] = by - ey;  py2[b] = by + ey;
            areat[b] = (2.0f * ex) * (2.0f * ey);
        }
    }

    // ---- warp bbox (xor-reduce: every lane gets the result) ----
    float bminx = fminf(fminf(px1[0], px1[1]), fminf(px1[2], px1[3]));
    float bminy = fminf(fminf(py1[0], py1[1]), fminf(py1[2], py1[3]));
    float bmaxx = fmaxf(fmaxf(px2[0], px2[1]), fmaxf(px2[2], px2[3]));
    float bmaxy = fmaxf(fmaxf(py2[0], py2[1]), fmaxf(py2[2], py2[3]));
#pragma unroll
    for (int off = 16; off > 0; off >>= 1) {
        bminx = fminf(bminx, __shfl_xor_sync(0xFFFFFFFFu, bminx, off));
        bminy = fminf(bminy, __shfl_xor_sync(0xFFFFFFFFu, bminy, off));
        bmaxx = fmaxf(bmaxx, __shfl_xor_sync(0xFFFFFFFFu, bmaxx, off));
        bmaxy = fmaxf(bmaxy, __shfl_xor_sync(0xFFFFFFFFu, bmaxy, off));
    }

    // ---- warp-private cull: lane tests targets lane and lane+32 ----
    __shared__ float4 s_cbox[8][NTGT];
    __shared__ float  s_care[8][NTGT];

    const int m0i = lane, m1i = lane + 32;
    bool h0 = (s_tx1[m0i] <= bmaxx) && (s_tx2[m0i] >= bminx) &&
              (s_ty1[m0i] <= bmaxy) && (s_ty2[m0i] >= bminy);
    bool h1 = (s_tx1[m1i] <= bmaxx) && (s_tx2[m1i] >= bminx) &&
              (s_ty1[m1i] <= bmaxy) && (s_ty2[m1i] >= bminy);

    unsigned mask0 = __ballot_sync(0xFFFFFFFFu, h0);
    unsigned mask1 = __ballot_sync(0xFFFFFFFFu, h1);
    const unsigned lt = (1u << lane) - 1u;
    const int base1 = __popc(mask0);
    if (h0) {
        int idx = __popc(mask0 & lt);
        s_cbox[w][idx] = make_float4(s_tx1[m0i], s_ty1[m0i],
                                     s_tx2[m0i], s_ty2[m0i]);
        s_care[w][idx] = s_tar[m0i];
    }
    if (h1) {
        int idx = base1 + __popc(mask1 & lt);
        s_cbox[w][idx] = make_float4(s_tx1[m1i], s_ty1[m1i],
                                     s_tx2[m1i], s_ty2[m1i]);
        s_care[w][idx] = s_tar[m1i];
    }
    __syncwarp();
    const int cnt = base1 + __popc(mask1);

    // ---- IoU over warp survivors ----
    float acc[4] = {0.f, 0.f, 0.f, 0.f};
    for (int m = 0; m < cnt; m++) {
        const float4 tb = s_cbox[w][m];
        const float  ta = s_care[w][m];
#pragma unroll
        for (int b = 0; b < 4; b++) {
            float wi = fminf(px2[b], tb.z) - fmaxf(px1[b], tb.x);
            float hi = fminf(py2[b], tb.w) - fmaxf(py1[b], tb.y);
            if (wi > 0.0f && hi > 0.0f) {
                float wh = wi * hi;
                acc[b] += __fdividef(wh, areat[b] + ta - wh);
            }
        }
    }

    float local = wlog[0] * acc[0] + wlog[1] * acc[1] +
                  wlog[2] * acc[2] + wlog[3] * acc[3];

    // ---- warp sum -> per-warp atomic; warp ticket; last warp publishes ----
#pragma unroll
    for (int off = 16; off > 0; off >>= 1)
        local += __shfl_down_sync(0xFFFFFFFFu, local, off);
    if (lane == 0) {
        atomicAdd(&g_accum, local);
        __threadfence();                           // order accum before ticket
        unsigned int t = atomicAdd(&g_done, 1u);
        if (t == NWARPTOT - 1) {
            float total = atomicAdd(&g_accum, 0.0f);
            out[0] = total;
            g_accum = 0.0f;                        // reset for next replay
            g_done  = 0u;
        }
    }
}

extern "C" void kernel_launch(void* const* d_in, const int* in_sizes, int n_in,
                              void* d_out, int out_size) {
    const float* psm = (const float*)d_in[0];
    const float* rm  = (const float*)d_in[1];
    const float* anc = (const float*)d_in[2];
    const float* Tm  = (const float*)d_in[3];
    const float* tgt = (const float*)d_in[4];
    float* out = (float*)d_out;

    loss_kernel<<<NBLK, TPB>>>(psm, rm, anc, Tm, tgt, out);
}

// round 13
// speedup vs baseline: 1.1548x; 1.1548x over previous
#include <cuda_runtime.h>
#include <math.h>

#define WDIM 512
#define LDIM 512
#define WL   (WDIM * LDIM)      // 262144 pixels
#define NTGT 64
#define TPB  256
// tile = 8 rows x 32 cols, 1 pixel per thread
#define NBLK 1024               // 64 i-tiles x 16 j-tiles

__device__ float        g_accum;  // zero-init; publisher resets
__device__ unsigned int g_done;   // zero-init; publisher resets

// logit(0.1) = ln(0.1/0.9)
#define LOGIT_THRESH (-2.1972245773362196f)

// ---------------------------------------------------------------------------
// Single kernel, 1 pixel x 2 anchors per thread (minimal register state ->
// 5 blocks/SM). Block-level target culling; per-block atomic scalar tail.
// ---------------------------------------------------------------------------
__global__ __launch_bounds__(TPB, 5) void loss_kernel(
    const float* __restrict__ psm,    // [2, W, L]
    const float* __restrict__ rm,     // [14, W, L]
    const float* __restrict__ anc,    // [W, L, 2, 7]
    const float* __restrict__ Tm,     // [4, 4]
    const float* __restrict__ target, // [64, 7]
    float* __restrict__ out)
{
    const int tid = threadIdx.x;

    // ---- tile -> pixel mapping: warp = 1 row x 32 cols (128B segments) ----
    const int tile_i = blockIdx.x >> 4;            // 0..63
    const int tile_j = blockIdx.x & 15;            // 0..15
    const int i = tile_i * 8 + (tid >> 5);         // row
    const int j = tile_j * 32 + (tid & 31);        // col
    const int pix = i * LDIM + j;

    // ---- front-batch streaming loads (16 x LDG.32, all 128B/warp) ----
    float rc[14];
#pragma unroll
    for (int c = 0; c < 14; c++)
        rc[c] = rm[(size_t)c * WL + pix];

    const float xlA = psm[pix];
    const float xlB = psm[WL + pix];

    // ---- anchor grid parameters (uniform loads, cached) ----
    const float x0   = anc[0];
    const float y0   = anc[1];
    const float cz   = anc[2];
    const float ah   = anc[3];
    const float aw   = anc[4];
    const float al   = anc[5];
    const float yaw0 = anc[6];
    const float yaw1 = anc[13];
    const float dxs  = anc[512 * 14] - x0;     // xs step (pixel (1,0))
    const float dys  = anc[14 + 1]   - y0;     // ys step (pixel (0,1))

    const float dg = sqrtf(aw * aw + al * al);
    const float ax = fmaf((float)i, dxs, x0);
    const float ay = fmaf((float)j, dys, y0);

    // ---- target standup boxes (threads 0..63) ----
    float tminx = 0.f, tminy = 0.f, tmaxx = 0.f, tmaxy = 0.f, tarea = 0.f;
    if (tid < NTGT) {
        const float* t = target + tid * 7;
        float X = t[0], Y = t[1];
        float w = t[4], l = t[5];
        float c, s;
        __sincosf(t[6], &s, &c);
        float ex = 0.5f * (fabsf(c) * l + fabsf(s) * w);
        float ey = 0.5f * (fabsf(s) * l + fabsf(c) * w);
        tminx = X - ex;  tmaxx = X + ex;
        tminy = Y - ey;  tmaxy = Y + ey;
        tarea = (2.0f * ex) * (2.0f * ey);
    }

    const float T00 = Tm[0], T01 = Tm[1], T02 = Tm[2], T03 = Tm[3];
    const float T10 = Tm[4], T11 = Tm[5], T12 = Tm[6], T13 = Tm[7];

    // ---- decode 2 boxes (anchor 0 / anchor 1) ----
    float px1[2], py1[2], px2[2], py2[2], areat[2], wlog[2];

#pragma unroll
    for (int a = 0; a < 2; a++) {
        float xl = (a == 0) ? xlA : xlB;
        wlog[a] = (xl > LOGIT_THRESH)
                    ? -__logf(1.0f + __expf(xl)) : 0.0f;

        float d0 = rc[a * 7 + 0];
        float d1 = rc[a * 7 + 1];
        float d2 = rc[a * 7 + 2];
        float d3 = rc[a * 7 + 3];
        float d4 = rc[a * 7 + 4];
        float d5 = rc[a * 7 + 5];
        float d6 = rc[a * 7 + 6];

        float X = fmaf(d0, dg, ax);
        float Y = fmaf(d1, dg, ay);
        float Z = fmaf(d2, ah, cz);
        float hh = __expf(d3) * ah;
        float ww = __expf(d4) * aw;
        float ll = __expf(d5) * al;

        float c, s;
        __sincosf(d6 + ((a == 0) ? yaw0 : yaw1), &s, &c);

        float bx = fmaf(T00, X, fmaf(T01, Y, fmaf(T02, Z, T03)));
        float by = fmaf(T10, X, fmaf(T11, Y, fmaf(T12, Z, T13)));
        float ex = 0.5f * (fabsf(fmaf(T00, c,  T01 * s)) * ll +
                           fabsf(fmaf(T01, c, -T00 * s)) * ww +
                           fabsf(T02) * hh);
        float ey = 0.5f * (fabsf(fmaf(T10, c,  T11 * s)) * ll +
                           fabsf(fmaf(T10 * -s, 1.0f, T11 * c)) * ww +
                           fabsf(T12) * hh);
        // NOTE: keep exact same formula as proven rounds:
        ey = 0.5f * (fabsf(fmaf(T10, c,  T11 * s)) * ll +
                     fabsf(fmaf(T11, c, -T10 * s)) * ww +
                     fabsf(T12) * hh);

        px1[a] = bx - ex;  px2[a] = bx + ex;
        py1[a] = by - ey;  py2[a] = by + ey;
        areat[a] = (2.0f * ex) * (2.0f * ey);
    }

    // ---- block bounding box over both boxes per thread ----
    float bminx = fminf(px1[0], px1[1]);
    float bminy = fminf(py1[0], py1[1]);
    float bmaxx = fmaxf(px2[0], px2[1]);
    float bmaxy = fmaxf(py2[0], py2[1]);

    __shared__ float s_minx[8], s_miny[8], s_maxx[8], s_maxy[8];
    __shared__ float s_bbox[4];
#pragma unroll
    for (int off = 16; off > 0; off >>= 1) {
        bminx = fminf(bminx, __shfl_xor_sync(0xFFFFFFFFu, bminx, off));
        bminy = fminf(bminy, __shfl_xor_sync(0xFFFFFFFFu, bminy, off));
        bmaxx = fmaxf(bmaxx, __shfl_xor_sync(0xFFFFFFFFu, bmaxx, off));
        bmaxy = fmaxf(bmaxy, __shfl_xor_sync(0xFFFFFFFFu, bmaxy, off));
    }
    const int lane = tid & 31;
    const int wid  = tid >> 5;
    if (lane == 0) {
        s_minx[wid] = bminx;  s_miny[wid] = bminy;
        s_maxx[wid] = bmaxx;  s_maxy[wid] = bmaxy;
    }
    __syncthreads();
    if (wid == 0) {
        float m0 = (lane < 8) ? s_minx[lane] :  1e30f;
        float m1 = (lane < 8) ? s_miny[lane] :  1e30f;
        float m2 = (lane < 8) ? s_maxx[lane] : -1e30f;
        float m3 = (lane < 8) ? s_maxy[lane] : -1e30f;
#pragma unroll
        for (int off = 4; off > 0; off >>= 1) {
            m0 = fminf(m0, __shfl_xor_sync(0xFFFFFFFFu, m0, off));
            m1 = fminf(m1, __shfl_xor_sync(0xFFFFFFFFu, m1, off));
            m2 = fmaxf(m2, __shfl_xor_sync(0xFFFFFFFFu, m2, off));
            m3 = fmaxf(m3, __shfl_xor_sync(0xFFFFFFFFu, m3, off));
        }
        if (lane == 0) {
            s_bbox[0] = m0;  s_bbox[1] = m1;  s_bbox[2] = m2;  s_bbox[3] = m3;
        }
    }
    __syncthreads();

    // ---- cull targets against block bbox ----
    __shared__ int    s_cnt;
    __shared__ float4 s_cbox[NTGT];
    __shared__ float  s_carea[NTGT];
    if (tid == 0) s_cnt = 0;
    __syncthreads();
    if (tid < NTGT) {
        bool hit = (tminx <= s_bbox[2]) && (tmaxx >= s_bbox[0]) &&
                   (tminy <= s_bbox[3]) && (tmaxy >= s_bbox[1]);
        if (hit) {
            int idx = atomicAdd(&s_cnt, 1);
            s_cbox[idx]  = make_float4(tminx, tminy, tmaxx, tmaxy);
            s_carea[idx] = tarea;
        }
    }
    __syncthreads();
    const int cnt = s_cnt;

    // ---- IoU over survivors for both boxes ----
    float acc0 = 0.0f, acc1 = 0.0f;
    for (int m = 0; m < cnt; m++) {
        const float4 tb = s_cbox[m];
        const float  ta = s_carea[m];
        {
            float wi = fminf(px2[0], tb.z) - fmaxf(px1[0], tb.x);
            float hi = fminf(py2[0], tb.w) - fmaxf(py1[0], tb.y);
            if (wi > 0.0f && hi > 0.0f) {
                float wh = wi * hi;
                acc0 += __fdividef(wh, areat[0] + ta - wh);
            }
        }
        {
            float wi = fminf(px2[1], tb.z) - fmaxf(px1[1], tb.x);
            float hi = fminf(py2[1], tb.w) - fmaxf(py1[1], tb.y);
            if (wi > 0.0f && hi > 0.0f) {
                float wh = wi * hi;
                acc1 += __fdividef(wh, areat[1] + ta - wh);
            }
        }
    }

    float local = wlog[0] * acc0 + wlog[1] * acc1;

    // ---- block sum -> per-block atomic; ticket; last block publishes ----
    __shared__ float red[8];
#pragma unroll
    for (int off = 16; off > 0; off >>= 1)
        local += __shfl_down_sync(0xFFFFFFFFu, local, off);
    if (lane == 0) red[wid] = local;
    __syncthreads();
    if (wid == 0) {
        float v = (lane < 8) ? red[lane] : 0.0f;
#pragma unroll
        for (int off = 4; off > 0; off >>= 1)
            v += __shfl_down_sync(0xFFFFFFFFu, v, off);
        if (lane == 0) {
            atomicAdd(&g_accum, v);
            __threadfence();                       // order accum before ticket
            unsigned int t = atomicAdd(&g_done, 1u);
            if (t == NBLK - 1) {
                float total = atomicAdd(&g_accum, 0.0f);
                out[0] = total;
                g_accum = 0.0f;                    // reset for next replay
                g_done  = 0u;
            }
        }
    }
}

extern "C" void kernel_launch(void* const* d_in, const int* in_sizes, int n_in,
                              void* d_out, int out_size) {
    const float* psm = (const float*)d_in[0];
    const float* rm  = (const float*)d_in[1];
    const float* anc = (const float*)d_in[2];
    const float* Tm  = (const float*)d_in[3];
    const float* tgt = (const float*)d_in[4];
    float* out = (float*)d_out;

    loss_kernel<<<NBLK, TPB>>>(psm, rm, anc, Tm, tgt, out);
}

// round 16
// speedup vs baseline: 1.3703x; 1.1866x over previous
#include <cuda_runtime.h>
#include <math.h>

#define WDIM 512
#define LDIM 512
#define WL   (WDIM * LDIM)      // 262144 pixels
#define NTGT 64
#define TPB  256
// tile = 16 rows x 32 cols; each thread handles 2 adjacent-j pixels
#define NBLK 512                // 32 i-tiles x 16 j-tiles

__device__ float        g_accum;  // zero-init; publisher resets
__device__ unsigned int g_done;   // zero-init; publisher resets

// logit(0.1) = ln(0.1/0.9)
#define LOGIT_THRESH (-2.1972245773362196f)

// ---------------------------------------------------------------------------
// R9 champion + MUFU reduction:
//  - softplus (wlog) deferred until after IoU, only when acc != 0 (~20% of px)
//  - exp(d3)/Z chain skipped under uniform branch when T02==T12==0
// ---------------------------------------------------------------------------
__global__ __launch_bounds__(TPB, 4) void loss_kernel(
    const float* __restrict__ psm,    // [2, W, L]
    const float* __restrict__ rm,     // [14, W, L]
    const float* __restrict__ anc,    // [W, L, 2, 7]
    const float* __restrict__ Tm,     // [4, 4]
    const float* __restrict__ target, // [64, 7]
    float* __restrict__ out)
{
    const int tid = threadIdx.x;

    // ---- tile -> pixel-pair mapping ----
    const int tile_i = blockIdx.x >> 4;            // 0..31
    const int tile_j = blockIdx.x & 15;            // 0..15
    const int i  = tile_i * 16 + (tid >> 4);       // row
    const int jp = tile_j * 16 + (tid & 15);       // pixel-pair index
    const int pix0 = i * LDIM + jp * 2;            // even pixel

    // ---- front-batch the streaming loads ----
    float2 rc[14];
#pragma unroll
    for (int c = 0; c < 14; c++)
        rc[c] = *(const float2*)(rm + (size_t)c * WL + pix0);

    const float2 sA = *(const float2*)(psm + pix0);        // anchor 0
    const float2 sB = *(const float2*)(psm + WL + pix0);   // anchor 1

    // ---- anchor grid parameters (uniform loads, cached) ----
    const float x0   = anc[0];
    const float y0   = anc[1];
    const float cz   = anc[2];
    const float ah   = anc[3];
    const float aw   = anc[4];
    const float al   = anc[5];
    const float yaw0 = anc[6];
    const float yaw1 = anc[13];
    const float dxs  = anc[512 * 14] - x0;
    const float dys  = anc[14 + 1]   - y0;

    const float dg = sqrtf(aw * aw + al * al);
    const float ax = fmaf((float)i, dxs, x0);
    const float ay_p[2] = { fmaf((float)(jp * 2),     dys, y0),
                            fmaf((float)(jp * 2 + 1), dys, y0) };

    // ---- target standup boxes (threads 0..63) ----
    float tminx = 0.f, tminy = 0.f, tmaxx = 0.f, tmaxy = 0.f, tarea = 0.f;
    if (tid < NTGT) {
        const float* t = target + tid * 7;
        float X = t[0], Y = t[1];
        float w = t[4], l = t[5];
        float c, s;
        __sincosf(t[6], &s, &c);
        float ex = 0.5f * (fabsf(c) * l + fabsf(s) * w);
        float ey = 0.5f * (fabsf(s) * l + fabsf(c) * w);
        tminx = X - ex;  tmaxx = X + ex;
        tminy = Y - ey;  tmaxy = Y + ey;
        tarea = (2.0f * ex) * (2.0f * ey);
    }

    const float T00 = Tm[0], T01 = Tm[1], T02 = Tm[2], T03 = Tm[3];
    const float T10 = Tm[4], T11 = Tm[5], T12 = Tm[6], T13 = Tm[7];
    // uniform: is T a pure z-rotation (no z coupling into x/y)?
    const bool flatT = (T02 == 0.0f) && (T12 == 0.0f);

    // ---- decode 4 boxes: b = p*2 + a ----
    float px1[4], py1[4], px2[4], py2[4], areat[4];

#pragma unroll
    for (int p = 0; p < 2; p++) {
#pragma unroll
        for (int a = 0; a < 2; a++) {
            const int b = p * 2 + a;

            float d0 = (p == 0) ? rc[a * 7 + 0].x : rc[a * 7 + 0].y;
            float d1 = (p == 0) ? rc[a * 7 + 1].x : rc[a * 7 + 1].y;
            float d2 = (p == 0) ? rc[a * 7 + 2].x : rc[a * 7 + 2].y;
            float d3 = (p == 0) ? rc[a * 7 + 3].x : rc[a * 7 + 3].y;
            float d4 = (p == 0) ? rc[a * 7 + 4].x : rc[a * 7 + 4].y;
            float d5 = (p == 0) ? rc[a * 7 + 5].x : rc[a * 7 + 5].y;
            float d6 = (p == 0) ? rc[a * 7 + 6].x : rc[a * 7 + 6].y;

            float X = fmaf(d0, dg, ax);
            float Y = fmaf(d1, dg, ay_p[p]);
            float ww = __expf(d4) * aw;
            float ll = __expf(d5) * al;

            // z-chain only when the transform couples z into x/y (uniform)
            float hh = 0.0f, Z = 0.0f;
            if (!flatT) {
                hh = __expf(d3) * ah;
                Z  = fmaf(d2, ah, cz);
            }

            float c, s;
            __sincosf(d6 + ((a == 0) ? yaw0 : yaw1), &s, &c);

            float bx = fmaf(T00, X, fmaf(T01, Y, fmaf(T02, Z, T03)));
            float by = fmaf(T10, X, fmaf(T11, Y, fmaf(T12, Z, T13)));
            float ex = 0.5f * (fabsf(fmaf(T00, c,  T01 * s)) * ll +
                               fabsf(fmaf(T01, c, -T00 * s)) * ww +
                               fabsf(T02) * hh);
            float ey = 0.5f * (fabsf(fmaf(T10, c,  T11 * s)) * ll +
                               fabsf(fmaf(T11, c, -T10 * s)) * ww +
                               fabsf(T12) * hh);

            px1[b] = bx - ex;  px2[b] = bx + ex;
            py1[b] = by - ey;  py2[b] = by + ey;
            areat[b] = (2.0f * ex) * (2.0f * ey);
        }
    }

    // ---- block bounding box over all 4 boxes per thread ----
    float bminx = fminf(fminf(px1[0], px1[1]), fminf(px1[2], px1[3]));
    float bminy = fminf(fminf(py1[0], py1[1]), fminf(py1[2], py1[3]));
    float bmaxx = fmaxf(fmaxf(px2[0], px2[1]), fmaxf(px2[2], px2[3]));
    float bmaxy = fmaxf(fmaxf(py2[0], py2[1]), fmaxf(py2[2], py2[3]));

    __shared__ float s_minx[8], s_miny[8], s_maxx[8], s_maxy[8];
    __shared__ float s_bbox[4];
#pragma unroll
    for (int off = 16; off > 0; off >>= 1) {
        bminx = fminf(bminx, __shfl_xor_sync(0xFFFFFFFFu, bminx, off));
        bminy = fminf(bminy, __shfl_xor_sync(0xFFFFFFFFu, bminy, off));
        bmaxx = fmaxf(bmaxx, __shfl_xor_sync(0xFFFFFFFFu, bmaxx, off));
        bmaxy = fmaxf(bmaxy, __shfl_xor_sync(0xFFFFFFFFu, bmaxy, off));
    }
    const int lane = tid & 31;
    const int wid  = tid >> 5;
    if (lane == 0) {
        s_minx[wid] = bminx;  s_miny[wid] = bminy;
        s_maxx[wid] = bmaxx;  s_maxy[wid] = bmaxy;
    }
    __syncthreads();
    if (wid == 0) {
        float m0 = (lane < 8) ? s_minx[lane] :  1e30f;
        float m1 = (lane < 8) ? s_miny[lane] :  1e30f;
        float m2 = (lane < 8) ? s_maxx[lane] : -1e30f;
        float m3 = (lane < 8) ? s_maxy[lane] : -1e30f;
#pragma unroll
        for (int off = 4; off > 0; off >>= 1) {
            m0 = fminf(m0, __shfl_xor_sync(0xFFFFFFFFu, m0, off));
            m1 = fminf(m1, __shfl_xor_sync(0xFFFFFFFFu, m1, off));
            m2 = fmaxf(m2, __shfl_xor_sync(0xFFFFFFFFu, m2, off));
            m3 = fmaxf(m3, __shfl_xor_sync(0xFFFFFFFFu, m3, off));
        }
        if (lane == 0) {
            s_bbox[0] = m0;  s_bbox[1] = m1;  s_bbox[2] = m2;  s_bbox[3] = m3;
        }
    }
    __syncthreads();

    // ---- cull targets against block bbox ----
    __shared__ int    s_cnt;
    __shared__ float4 s_cbox[NTGT];
    __shared__ float  s_carea[NTGT];
    if (tid == 0) s_cnt = 0;
    __syncthreads();
    if (tid < NTGT) {
        bool hit = (tminx <= s_bbox[2]) && (tmaxx >= s_bbox[0]) &&
                   (tminy <= s_bbox[3]) && (tmaxy >= s_bbox[1]);
        if (hit) {
            int idx = atomicAdd(&s_cnt, 1);
            s_cbox[idx]  = make_float4(tminx, tminy, tmaxx, tmaxy);
            s_carea[idx] = tarea;
        }
    }
    __syncthreads();
    const int cnt = s_cnt;

    // ---- IoU over survivors for all 4 boxes ----
    float acc[4] = {0.f, 0.f, 0.f, 0.f};
    for (int m = 0; m < cnt; m++) {
        const float4 tb = s_cbox[m];
        const float  ta = s_carea[m];
#pragma unroll
        for (int b = 0; b < 4; b++) {
            float wi = fminf(px2[b], tb.z) - fmaxf(px1[b], tb.x);
            float hi = fminf(py2[b], tb.w) - fmaxf(py1[b], tb.y);
            if (wi > 0.0f && hi > 0.0f) {
                float wh = wi * hi;
                acc[b] += __fdividef(wh, areat[b] + ta - wh);
            }
        }
    }

    // ---- deferred wlog: softplus only where acc != 0 (~20% of pixels) ----
    float local = 0.0f;
    {
        const float xls[4] = { sA.x, sB.x, sA.y, sB.y };  // b = p*2+a order
#pragma unroll
        for (int b = 0; b < 4; b++) {
            if (acc[b] != 0.0f) {
                float xl = xls[b];
                if (xl > LOGIT_THRESH)
                    local -= acc[b] * __logf(1.0f + __expf(xl));
            }
        }
    }

    // ---- block sum -> per-block atomic; ticket; last block publishes ----
    __shared__ float red[8];
#pragma unroll
    for (int off = 16; off > 0; off >>= 1)
        local += __shfl_down_sync(0xFFFFFFFFu, local, off);
    if (lane == 0) red[wid] = local;
    __syncthreads();
    if (wid == 0) {
        float v = (lane < 8) ? red[lane] : 0.0f;
#pragma unroll
        for (int off = 4; off > 0; off >>= 1)
            v += __shfl_down_sync(0xFFFFFFFFu, v, off);
        if (lane == 0) {
            atomicAdd(&g_accum, v);
            __threadfence();                       // order accum before ticket
            unsigned int t = atomicAdd(&g_done, 1u);
            if (t == NBLK - 1) {
                float total = atomicAdd(&g_accum, 0.0f);
                out[0] = total;
                g_accum = 0.0f;                    // reset for next replay
                g_done  = 0u;
            }
        }
    }
}

extern "C" void kernel_launch(void* const* d_in, const int* in_sizes, int n_in,
                              void* d_out, int out_size) {
    const float* psm = (const float*)d_in[0];
    const float* rm  = (const float*)d_in[1];
    const float* anc = (const float*)d_in[2];
    const float* Tm  = (const float*)d_in[3];
    const float* tgt = (const float*)d_in[4];
    float* out = (float*)d_out;

    loss_kernel<<<NBLK, TPB>>>(psm, rm, anc, Tm, tgt, out);
}